// round 8
// baseline (speedup 1.0000x reference)
#include <cuda_runtime.h>
#include <cuda_fp16.h>
#include <math.h>

// ---------------------------------------------------------------------------
// EvidentialGNN3D — dest-range bucketed, smem-accumulated formulation.
//  Build once/launch:
//    bucket(b) = contiguous dest-node range (~98 nodes); edges coarse-sorted
//    into bucket-contiguous 16B records {dot1,dot2,len(fp16),dloc(u16),src}.
//  Per round:
//    k_h      : h[n] = state[n]@Ws + b + sum|c_n|*W11 (fp16, one 32B sector)
//    k_edge_b : CTA b streams its bucket, gathers h[src], accumulates msgs in
//               SMEM (atomicAdd, stride-11 rows), adds to its state rows.
//  No global atomics in rounds.
// ---------------------------------------------------------------------------

#define NMAX   200064
#define EMAX   6400000
#define GMAX   2048
#define NBUCK  2048
#define HBLK   256      // histogram/scatter blocks (chunked edge partition)
#define MAXNB  112      // max nodes per bucket (98 + margin)

struct __align__(32) HRow { uint4 a; uint2 b; uint2 pad; };

__device__ float4 g_state[NMAX * 3];    // (N,12) state, in place
__device__ HRow   g_hp[NMAX];           // h packed: 10 x fp16 in one 32B sector
__device__ float4 g_pc[NMAX];           // (x,y,z,sum|c|)
__device__ float4 g_gs[GMAX * 3];       // per-graph accum
__device__ uint4  g_rec2[EMAX];         // bucket-sorted records
__device__ int    g_bh[HBLK * NBUCK];   // per-(bucket,block) hist / offsets [b*HBLK+i]
__device__ int    g_btot[NBUCK];        // bucket totals
__device__ int    g_bstart[NBUCK + 1];  // bucket edge starts (exclusive scan)
__device__ float  g_w[30];              // W rows 10 (len), 12 (dot1), 13 (dot2)

__device__ __forceinline__ float tanh_fast(float x) {
    float e = __expf(2.0f * x);
    return 1.0f - __fdividef(2.0f, e + 1.0f);
}
__device__ __forceinline__ void red_add4(float* p, float a, float b, float c, float d) {
    unsigned long long gp = __cvta_generic_to_global((void*)p);
    asm volatile("red.global.add.v4.f32 [%0], {%1,%2,%3,%4};"
                 :: "l"(gp), "f"(a), "f"(b), "f"(c), "f"(d) : "memory");
}
__device__ __forceinline__ void red_add2(float* p, float a, float b) {
    unsigned long long gp = __cvta_generic_to_global((void*)p);
    asm volatile("red.global.add.v2.f32 [%0], {%1,%2};"
                 :: "l"(gp), "f"(a), "f"(b) : "memory");
}

__device__ __forceinline__ int bucket_of(int n, int N) {
    return (int)(((long long)n * NBUCK) / N);
}
__device__ __forceinline__ int bucket_n0(int b, int N) {
    return (int)(((long long)b * N + NBUCK - 1) / NBUCK);
}

__device__ __forceinline__ void store_h(int n, const float* h) {
    __half2 p0 = __floats2half2_rn(h[0], h[1]);
    __half2 p1 = __floats2half2_rn(h[2], h[3]);
    __half2 p2 = __floats2half2_rn(h[4], h[5]);
    __half2 p3 = __floats2half2_rn(h[6], h[7]);
    __half2 p4 = __floats2half2_rn(h[8], h[9]);
    HRow r;
    r.a.x = *(unsigned int*)&p0;
    r.a.y = *(unsigned int*)&p1;
    r.a.z = *(unsigned int*)&p2;
    r.a.w = *(unsigned int*)&p3;
    r.b.x = *(unsigned int*)&p4;
    r.b.y = 0u;
    r.pad.x = 0u; r.pad.y = 0u;
    g_hp[n] = r;
}

// ---- init: pc, h0 = b + sum|c|*W11 (state=0), zero state & graph accum ----
__global__ void k_init(const float* __restrict__ coords,
                       const float* __restrict__ Wm, const float* __restrict__ bm,
                       int N) {
    int n = blockIdx.x * blockDim.x + threadIdx.x;
    float4 z4 = make_float4(0.f, 0.f, 0.f, 0.f);
    if (n < N) {
        float x = coords[3 * n + 0];
        float y = coords[3 * n + 1];
        float z = coords[3 * n + 2];
        float sa = fabsf(x) + fabsf(y) + fabsf(z);
        g_pc[n] = make_float4(x, y, z, sa);
        float h[10];
#pragma unroll
        for (int j = 0; j < 10; j++)
            h[j] = fmaf(sa, __ldg(&Wm[110 + j]), __ldg(&bm[j]));
        store_h(n, h);
        g_state[n * 3 + 0] = z4;
        g_state[n * 3 + 1] = z4;
        g_state[n * 3 + 2] = z4;
    }
    if (n < GMAX) {
        g_gs[n * 3 + 0] = z4;
        g_gs[n * 3 + 1] = z4;
        g_gs[n * 3 + 2] = z4;
    }
}

// ---- per-block bucket histogram (chunked edge partition) ----
__global__ void __launch_bounds__(256)
k_bhist(const int* __restrict__ eto, int E, int CH, int N) {
    __shared__ int sh[NBUCK];
    int i = blockIdx.x;
    for (int b = threadIdx.x; b < NBUCK; b += blockDim.x) sh[b] = 0;
    __syncthreads();
    int e0 = i * CH;
    int e1 = e0 + CH; if (e1 > E) e1 = E;
    for (int e = e0 + threadIdx.x; e < e1; e += blockDim.x) {
        int b = bucket_of(__ldg(&eto[e]), N);
        atomicAdd(&sh[b], 1);
    }
    __syncthreads();
    for (int b = threadIdx.x; b < NBUCK; b += blockDim.x)
        g_bh[b * HBLK + i] = sh[b];
}

// ---- in-bucket exclusive scan over blocks (warp per bucket) ----
__global__ void k_s1() {
    int wid = threadIdx.x >> 5;
    int lane = threadIdx.x & 31;
    int b = blockIdx.x * 8 + wid;           // grid = NBUCK/8 blocks of 256
    int base = b * HBLK + lane * 8;
    int v[8];
    int run = 0;
#pragma unroll
    for (int k = 0; k < 8; k++) {
        int t = g_bh[base + k];
        v[k] = run;
        run += t;
    }
    int x = run;
#pragma unroll
    for (int d = 1; d < 32; d <<= 1) {
        int y = __shfl_up_sync(0xFFFFFFFFu, x, d);
        if (lane >= d) x += y;
    }
    int wex = x - run;
#pragma unroll
    for (int k = 0; k < 8; k++)
        g_bh[base + k] = wex + v[k];
    if (lane == 31) g_btot[b] = x;
}

// ---- scan bucket totals (1 block, 1024 threads, 2 each) ----
__global__ void k_s2() {
    __shared__ int sm[1024];
    int t = threadIdx.x;
    int a = g_btot[2 * t], b2 = g_btot[2 * t + 1];
    int s = a + b2;
    sm[t] = s; __syncthreads();
    for (int d = 1; d < 1024; d <<= 1) {
        int add = (t >= d) ? sm[t - d] : 0;
        __syncthreads();
        sm[t] += add;
        __syncthreads();
    }
    int incl = sm[t];
    int excl = incl - s;
    g_bstart[2 * t] = excl;
    g_bstart[2 * t + 1] = excl + a;
    if (t == 1023) g_bstart[2048] = incl;
}

// ---- scatter into bucket-sorted records (smem cursors, geo fused) ----
__global__ void __launch_bounds__(256)
k_bbuild(const int* __restrict__ efrom, const int* __restrict__ eto,
         const float* __restrict__ elen, const float* __restrict__ evec,
         int E, int CH, int N) {
    __shared__ int scur[NBUCK];
    int i = blockIdx.x;
    for (int b = threadIdx.x; b < NBUCK; b += blockDim.x)
        scur[b] = g_bstart[b] + g_bh[b * HBLK + i];
    __syncthreads();
    int e0 = i * CH;
    int e1 = e0 + CH; if (e1 > E) e1 = E;
    for (int e = e0 + threadIdx.x; e < e1; e += blockDim.x) {
        int f = __ldg(&efrom[e]);
        int t = __ldg(&eto[e]);
        float4 cf = g_pc[f];
        float4 ct = g_pc[t];
        float len = __ldg(&elen[e]);
        float v0 = __ldg(&evec[3 * e + 0]);
        float v1 = __ldg(&evec[3 * e + 1]);
        float v2 = __ldg(&evec[3 * e + 2]);
        float dot1 = fmaf(cf.x, ct.x, fmaf(cf.y, ct.y, cf.z * ct.z));
        float dot2 = fmaf(cf.x, v0, fmaf(cf.y, v1, cf.z * v2));
        int b = bucket_of(t, N);
        int dloc = t - bucket_n0(b, N);
        int pos = atomicAdd(&scur[b], 1);
        uint4 r;
        r.x = __float_as_uint(dot1);
        r.y = __float_as_uint(dot2);
        r.z = (unsigned int)__half_as_ushort(__float2half_rn(len))
            | ((unsigned int)dloc << 16);
        r.w = (unsigned int)f;
        g_rec2[pos] = r;
    }
}

__global__ void k_wld(const float* __restrict__ Wm) {
    int j = threadIdx.x;
    if (j < 10) {
        g_w[j]      = Wm[100 + j];
        g_w[10 + j] = Wm[120 + j];
        g_w[20 + j] = Wm[130 + j];
    }
}

// ---- per-node h = state@Ws + b + sa*W11 (fp16-packed) ----
__global__ void k_h(const float* __restrict__ Wm, const float* __restrict__ bm,
                    int N) {
    int n = blockIdx.x * blockDim.x + threadIdx.x;
    if (n >= N) return;
    const float4* srow = &g_state[n * 3];
    float4 s0 = srow[0], s1 = srow[1], s2 = srow[2];
    float s[10] = { s0.x, s0.y, s0.z, s0.w, s1.x, s1.y, s1.z, s1.w, s2.x, s2.y };
    float sa = g_pc[n].w;
    float h[10];
#pragma unroll
    for (int j = 0; j < 10; j++) {
        float acc = fmaf(sa, __ldg(&Wm[110 + j]), __ldg(&bm[j]));
#pragma unroll
        for (int i = 0; i < 10; i++)
            acc = fmaf(s[i], __ldg(&Wm[i * 10 + j]), acc);
        h[j] = acc;
    }
    store_h(n, h);
}

// ---- per-round bucket kernel: smem accumulation, no global atomics ----
__global__ void __launch_bounds__(256)
k_edge_b(int N) {
    __shared__ float sacc[MAXNB * 11];
    int b = blockIdx.x;
    int n0 = bucket_n0(b, N);
    int n1 = bucket_n0(b + 1, N); if (n1 > N) n1 = N;
    int cnt = n1 - n0;
    for (int i = threadIdx.x; i < cnt * 11; i += blockDim.x) sacc[i] = 0.f;

    float wl[10], w2[10], w3[10];
#pragma unroll
    for (int j = 0; j < 10; j++) {
        wl[j] = g_w[j];
        w2[j] = g_w[10 + j];
        w3[j] = g_w[20 + j];
    }
    __syncthreads();

    int e0 = g_bstart[b];
    int e1 = g_bstart[b + 1];
    for (int e = e0 + threadIdx.x; e < e1; e += blockDim.x) {
        uint4 r = __ldcs(&g_rec2[e]);
        float dot1 = __uint_as_float(r.x);
        float dot2 = __uint_as_float(r.y);
        float len = __half2float(__ushort_as_half((unsigned short)(r.z & 0xFFFFu)));
        int dloc = (int)(r.z >> 16);
        int f = (int)r.w;
        const HRow* hp = &g_hp[f];
        uint4 u = __ldg(&hp->a);
        uint2 v = __ldg(&hp->b);
        float2 a0 = __half22float2(*(__half2*)&u.x);
        float2 a1 = __half22float2(*(__half2*)&u.y);
        float2 a2 = __half22float2(*(__half2*)&u.z);
        float2 a3 = __half22float2(*(__half2*)&u.w);
        float2 a4 = __half22float2(*(__half2*)&v.x);
        float hv[10] = { a0.x, a0.y, a1.x, a1.y, a2.x, a2.y, a3.x, a3.y, a4.x, a4.y };
        float* base = &sacc[dloc * 11];
#pragma unroll
        for (int j = 0; j < 10; j++) {
            float a = fmaf(len, wl[j], fmaf(dot1, w2[j], fmaf(dot2, w3[j], hv[j])));
            atomicAdd(&base[j], tanh_fast(a));
        }
    }
    __syncthreads();

    // exclusive node range: plain read-modify-write
    for (int k = threadIdx.x; k < cnt; k += blockDim.x) {
        float4* srow = &g_state[(n0 + k) * 3];
        float4 s0 = srow[0], s1 = srow[1], s2 = srow[2];
        const float* p = &sacc[k * 11];
        s0.x += p[0]; s0.y += p[1]; s0.z += p[2]; s0.w += p[3];
        s1.x += p[4]; s1.y += p[5]; s1.z += p[6]; s1.w += p[7];
        s2.x += p[8]; s2.y += p[9];
        srow[0] = s0; srow[1] = s1; srow[2] = s2;
    }
}

// ---- graph segment sum ----
__global__ void k_graph(const int* __restrict__ gidx, int N) {
    int n = blockIdx.x * blockDim.x + threadIdx.x;
    if (n >= N) return;
    int g = gidx[n];
    const float4* srow = &g_state[n * 3];
    float4 s0 = srow[0], s1 = srow[1], s2 = srow[2];
    float* dst = (float*)&g_gs[g * 3];
    red_add4(dst,     s0.x, s0.y, s0.z, s0.w);
    red_add4(dst + 4, s1.x, s1.y, s1.z, s1.w);
    red_add2(dst + 8, s2.x, s2.y);
}

__device__ __forceinline__ float softplus_acc(float x) {
    if (x > 20.f) return x;
    return log1pf(expf(x));
}

__global__ void k_out(const float* __restrict__ Wo, const float* __restrict__ bo,
                      float* __restrict__ out, int G) {
    int g = blockIdx.x * blockDim.x + threadIdx.x;
    if (g >= G) return;
    const float* gs = (const float*)&g_gs[g * 3];
    float e[4];
#pragma unroll
    for (int j = 0; j < 4; j++) {
        float acc = __ldg(&bo[j]);
#pragma unroll
        for (int i = 0; i < 10; i++)
            acc = fmaf(gs[i], __ldg(&Wo[i * 4 + j]), acc);
        e[j] = acc;
    }
    out[4 * g + 0] = e[0];
    out[4 * g + 1] = softplus_acc(e[1]);
    out[4 * g + 2] = softplus_acc(e[2]) + 1.0f;
    out[4 * g + 3] = softplus_acc(e[3]);
}

extern "C" void kernel_launch(void* const* d_in, const int* in_sizes, int n_in,
                              void* d_out, int out_size) {
    const float* coords = (const float*)d_in[0];
    const float* elen   = (const float*)d_in[1];
    const float* evec   = (const float*)d_in[2];
    const float* Wm     = (const float*)d_in[3];
    const float* bm     = (const float*)d_in[4];
    const float* Wo     = (const float*)d_in[5];
    const float* bo     = (const float*)d_in[6];
    const int*   efrom  = (const int*)d_in[7];
    const int*   eto    = (const int*)d_in[8];
    const int*   gidx   = (const int*)d_in[9];
    float* out = (float*)d_out;

    int E = in_sizes[7];
    int N = in_sizes[9];
    int G = out_size / 4;

    const int TB = 256;
    int init_count = (N > GMAX) ? N : GMAX;
    int init_blocks = (init_count + TB - 1) / TB;
    int node_blocks = (N + TB - 1) / TB;
    int CH = (E + HBLK - 1) / HBLK;     // edges per histogram/scatter block
    int gblocks = (G + TB - 1) / TB;

    // ---- build ----
    k_init<<<init_blocks, TB>>>(coords, Wm, bm, N);
    k_bhist<<<HBLK, TB>>>(eto, E, CH, N);
    k_s1<<<NBUCK / 8, 256>>>();
    k_s2<<<1, 1024>>>();
    k_bbuild<<<HBLK, TB>>>(efrom, eto, elen, evec, E, CH, N);
    k_wld<<<1, 32>>>(Wm);

    // ---- rounds ----
    k_edge_b<<<NBUCK, TB>>>(N);          // round 0 (h = h0 from init)
    k_h<<<node_blocks, TB>>>(Wm, bm, N);
    k_edge_b<<<NBUCK, TB>>>(N);          // round 1
    k_h<<<node_blocks, TB>>>(Wm, bm, N);
    k_edge_b<<<NBUCK, TB>>>(N);          // round 2

    // ---- readout ----
    k_graph<<<node_blocks, TB>>>(gidx, N);
    k_out<<<gblocks, TB>>>(Wo, bo, out, G);
}

// round 9
// speedup vs baseline: 1.7563x; 1.7563x over previous
#include <cuda_runtime.h>
#include <cuda_fp16.h>
#include <math.h>

// ---------------------------------------------------------------------------
// EvidentialGNN3D — unsorted, geo-precomputed, in-place RED formulation (R7)
// + packed dst (no eto stream) + unclobbered REDs + 2x unroll for MLP.
//  rec[e] = { dot1 f32, dot2 f32, len(f16)|dst_lo16, src(18b)|dst_hi2<<18 }
//  Per round:
//    k_h   : h[n] = state[n]@Ws + b + sum|c_n|*W11  (fp16, one 32B sector)
//    k_edge: m = tanh(h[src] + geo@Wg); red.global.add.v4/v2 into state[dst]
// ---------------------------------------------------------------------------

#define NMAX 200064
#define EMAX 6400000
#define GMAX 2048
#define SDP  12

struct __align__(32) HRow { uint4 a; uint2 b; uint2 pad; };

__device__ float4 g_state[NMAX * 3];   // (N,12) state, updated in place
__device__ HRow   g_hp[NMAX];          // h packed: 10 x fp16 in one 32B sector
__device__ float4 g_pc[NMAX];          // (x,y,z,sum|c|)
__device__ float4 g_gs[GMAX * 3];      // per-graph accum
__device__ uint4  g_rec[EMAX];         // packed records
__device__ float  g_w[30];             // W rows 10 (len), 12 (dot1), 13 (dot2)

__device__ __forceinline__ float tanh_fast(float x) {
    float e = __expf(2.0f * x);
    return 1.0f - __fdividef(2.0f, e + 1.0f);
}
// NOTE: no "memory" clobber — allows load hoisting / software pipelining.
// Nothing in this kernel reads g_state; inter-kernel ordering is implicit.
__device__ __forceinline__ void red_add4(float* p, float a, float b, float c, float d) {
    unsigned long long gp = __cvta_generic_to_global((void*)p);
    asm volatile("red.global.add.v4.f32 [%0], {%1,%2,%3,%4};"
                 :: "l"(gp), "f"(a), "f"(b), "f"(c), "f"(d));
}
__device__ __forceinline__ void red_add2(float* p, float a, float b) {
    unsigned long long gp = __cvta_generic_to_global((void*)p);
    asm volatile("red.global.add.v2.f32 [%0], {%1,%2};"
                 :: "l"(gp), "f"(a), "f"(b));
}

__device__ __forceinline__ void store_h(int n, const float* h) {
    __half2 p0 = __floats2half2_rn(h[0], h[1]);
    __half2 p1 = __floats2half2_rn(h[2], h[3]);
    __half2 p2 = __floats2half2_rn(h[4], h[5]);
    __half2 p3 = __floats2half2_rn(h[6], h[7]);
    __half2 p4 = __floats2half2_rn(h[8], h[9]);
    HRow r;
    r.a.x = *(unsigned int*)&p0;
    r.a.y = *(unsigned int*)&p1;
    r.a.z = *(unsigned int*)&p2;
    r.a.w = *(unsigned int*)&p3;
    r.b.x = *(unsigned int*)&p4;
    r.b.y = 0u;
    r.pad.x = 0u; r.pad.y = 0u;
    g_hp[n] = r;
}

// ---- init: pc, h0 = b + sum|c|*W11 (state=0), zero state & graph accum ----
__global__ void k_init(const float* __restrict__ coords,
                       const float* __restrict__ Wm, const float* __restrict__ bm,
                       int N) {
    int n = blockIdx.x * blockDim.x + threadIdx.x;
    float4 z4 = make_float4(0.f, 0.f, 0.f, 0.f);
    if (n < N) {
        float x = coords[3 * n + 0];
        float y = coords[3 * n + 1];
        float z = coords[3 * n + 2];
        float sa = fabsf(x) + fabsf(y) + fabsf(z);
        g_pc[n] = make_float4(x, y, z, sa);
        float h[10];
#pragma unroll
        for (int j = 0; j < 10; j++)
            h[j] = fmaf(sa, __ldg(&Wm[110 + j]), __ldg(&bm[j]));
        store_h(n, h);
        g_state[n * 3 + 0] = z4;
        g_state[n * 3 + 1] = z4;
        g_state[n * 3 + 2] = z4;
    }
    if (n < GMAX) {
        g_gs[n * 3 + 0] = z4;
        g_gs[n * 3 + 1] = z4;
        g_gs[n * 3 + 2] = z4;
    }
}

// ---- one-time geo precompute + id packing (coalesced) ----
__global__ void k_geo(const int* __restrict__ efrom, const int* __restrict__ eto,
                      const float* __restrict__ elen, const float* __restrict__ evec,
                      int E) {
    int e = blockIdx.x * blockDim.x + threadIdx.x;
    if (e >= E) return;
    int f = __ldg(&efrom[e]);
    int t = __ldg(&eto[e]);
    float4 cf = g_pc[f];
    float4 ct = g_pc[t];
    float len = __ldg(&elen[e]);
    float v0 = __ldg(&evec[3 * e + 0]);
    float v1 = __ldg(&evec[3 * e + 1]);
    float v2 = __ldg(&evec[3 * e + 2]);
    float dot1 = fmaf(cf.x, ct.x, fmaf(cf.y, ct.y, cf.z * ct.z));
    float dot2 = fmaf(cf.x, v0, fmaf(cf.y, v1, cf.z * v2));
    uint4 r;
    r.x = __float_as_uint(dot1);
    r.y = __float_as_uint(dot2);
    r.z = (unsigned int)__half_as_ushort(__float2half_rn(len))
        | (((unsigned int)t & 0xFFFFu) << 16);
    r.w = (unsigned int)f | (((unsigned int)t >> 16) << 18);
    g_rec[e] = r;
}

__global__ void k_wld(const float* __restrict__ Wm) {
    int j = threadIdx.x;
    if (j < 10) {
        g_w[j]      = Wm[100 + j];
        g_w[10 + j] = Wm[120 + j];
        g_w[20 + j] = Wm[130 + j];
    }
}

// ---- per-node h = state@Ws + b + sa*W11 (fp16-packed) ----
__global__ void k_h(const float* __restrict__ Wm, const float* __restrict__ bm,
                    int N) {
    int n = blockIdx.x * blockDim.x + threadIdx.x;
    if (n >= N) return;
    const float4* srow = &g_state[n * 3];
    float4 s0 = srow[0], s1 = srow[1], s2 = srow[2];
    float s[10] = { s0.x, s0.y, s0.z, s0.w, s1.x, s1.y, s1.z, s1.w, s2.x, s2.y };
    float sa = g_pc[n].w;
    float h[10];
#pragma unroll
    for (int j = 0; j < 10; j++) {
        float acc = fmaf(sa, __ldg(&Wm[110 + j]), __ldg(&bm[j]));
#pragma unroll
        for (int i = 0; i < 10; i++)
            acc = fmaf(s[i], __ldg(&Wm[i * 10 + j]), acc);
        h[j] = acc;
    }
    store_h(n, h);
}

// ---- per-edge body ----
__device__ __forceinline__ void edge_body(uint4 r, const float* wl,
                                          const float* w2, const float* w3,
                                          float* stt) {
    float dot1 = __uint_as_float(r.x);
    float dot2 = __uint_as_float(r.y);
    float len = __half2float(__ushort_as_half((unsigned short)(r.z & 0xFFFFu)));
    int t = (int)(r.z >> 16) | (int)(((r.w >> 18) & 3u) << 16);
    int f = (int)(r.w & 0x3FFFFu);
    const HRow* hp = &g_hp[f];
    uint4 u = __ldg(&hp->a);
    uint2 v = __ldg(&hp->b);
    float2 a0 = __half22float2(*(__half2*)&u.x);
    float2 a1 = __half22float2(*(__half2*)&u.y);
    float2 a2 = __half22float2(*(__half2*)&u.z);
    float2 a3 = __half22float2(*(__half2*)&u.w);
    float2 a4 = __half22float2(*(__half2*)&v.x);
    float hv[10] = { a0.x, a0.y, a1.x, a1.y, a2.x, a2.y, a3.x, a3.y, a4.x, a4.y };
    float m[10];
#pragma unroll
    for (int j = 0; j < 10; j++) {
        float a = fmaf(len, wl[j], fmaf(dot1, w2[j], fmaf(dot2, w3[j], hv[j])));
        m[j] = tanh_fast(a);
    }
    float* dst = stt + (size_t)t * SDP;
    red_add4(dst,     m[0], m[1], m[2], m[3]);
    red_add4(dst + 4, m[4], m[5], m[6], m[7]);
    red_add2(dst + 8, m[8], m[9]);
}

// ---- per-edge pass: 2x unrolled, pipelined loads, in-place REDs ----
__global__ void __launch_bounds__(256)
k_edge(int E, int T) {
    int tid = blockIdx.x * blockDim.x + threadIdx.x;
    float wl[10], w2[10], w3[10];
#pragma unroll
    for (int j = 0; j < 10; j++) {
        wl[j] = g_w[j];
        w2[j] = g_w[10 + j];
        w3[j] = g_w[20 + j];
    }
    float* stt = (float*)g_state;
    int e = tid;
    // pairs: process e and e+T together to raise MLP
    for (; e + T < E; e += 2 * T) {
        uint4 r0 = __ldcs(&g_rec[e]);
        uint4 r1 = __ldcs(&g_rec[e + T]);
        edge_body(r0, wl, w2, w3, stt);
        edge_body(r1, wl, w2, w3, stt);
    }
    if (e < E) {
        uint4 r0 = __ldcs(&g_rec[e]);
        edge_body(r0, wl, w2, w3, stt);
    }
}

// ---- graph segment sum ----
__global__ void k_graph(const int* __restrict__ gidx, int N) {
    int n = blockIdx.x * blockDim.x + threadIdx.x;
    if (n >= N) return;
    int g = gidx[n];
    const float4* srow = &g_state[n * 3];
    float4 s0 = srow[0], s1 = srow[1], s2 = srow[2];
    float* dst = (float*)&g_gs[g * 3];
    red_add4(dst,     s0.x, s0.y, s0.z, s0.w);
    red_add4(dst + 4, s1.x, s1.y, s1.z, s1.w);
    red_add2(dst + 8, s2.x, s2.y);
}

__device__ __forceinline__ float softplus_acc(float x) {
    if (x > 20.f) return x;
    return log1pf(expf(x));
}

__global__ void k_out(const float* __restrict__ Wo, const float* __restrict__ bo,
                      float* __restrict__ out, int G) {
    int g = blockIdx.x * blockDim.x + threadIdx.x;
    if (g >= G) return;
    const float* gs = (const float*)&g_gs[g * 3];
    float e[4];
#pragma unroll
    for (int j = 0; j < 4; j++) {
        float acc = __ldg(&bo[j]);
#pragma unroll
        for (int i = 0; i < 10; i++)
            acc = fmaf(gs[i], __ldg(&Wo[i * 4 + j]), acc);
        e[j] = acc;
    }
    out[4 * g + 0] = e[0];
    out[4 * g + 1] = softplus_acc(e[1]);
    out[4 * g + 2] = softplus_acc(e[2]) + 1.0f;
    out[4 * g + 3] = softplus_acc(e[3]);
}

extern "C" void kernel_launch(void* const* d_in, const int* in_sizes, int n_in,
                              void* d_out, int out_size) {
    const float* coords = (const float*)d_in[0];
    const float* elen   = (const float*)d_in[1];
    const float* evec   = (const float*)d_in[2];
    const float* Wm     = (const float*)d_in[3];
    const float* bm     = (const float*)d_in[4];
    const float* Wo     = (const float*)d_in[5];
    const float* bo     = (const float*)d_in[6];
    const int*   efrom  = (const int*)d_in[7];
    const int*   eto    = (const int*)d_in[8];
    const int*   gidx   = (const int*)d_in[9];
    float* out = (float*)d_out;

    int E = in_sizes[7];
    int N = in_sizes[9];
    int G = out_size / 4;

    const int TB = 256;
    int init_count = (N > GMAX) ? N : GMAX;
    int init_blocks = (init_count + TB - 1) / TB;
    int node_blocks = (N + TB - 1) / TB;
    int edge_blocks1 = (E + TB - 1) / TB;
    long ethreads = ((long)E + 3) / 4;              // 4 edges/thread
    int eblocks = (int)((ethreads + TB - 1) / TB);
    int T = eblocks * TB;
    int gblocks = (G + TB - 1) / TB;

    k_init<<<init_blocks, TB>>>(coords, Wm, bm, N);
    k_geo<<<edge_blocks1, TB>>>(efrom, eto, elen, evec, E);
    k_wld<<<1, 32>>>(Wm);

    // round 0 (h = h0 from init), REDs accumulate in place
    k_edge<<<eblocks, TB>>>(E, T);
    // rounds 1, 2
    k_h<<<node_blocks, TB>>>(Wm, bm, N);
    k_edge<<<eblocks, TB>>>(E, T);
    k_h<<<node_blocks, TB>>>(Wm, bm, N);
    k_edge<<<eblocks, TB>>>(E, T);

    k_graph<<<node_blocks, TB>>>(gidx, N);
    k_out<<<gblocks, TB>>>(Wo, bo, out, G);
}

// round 10
// speedup vs baseline: 1.9099x; 1.0874x over previous
#include <cuda_runtime.h>
#include <cuda_fp16.h>
#include <math.h>

// ---------------------------------------------------------------------------
// EvidentialGNN3D — geo-precomputed, round-0 fused into the build.
//  k_init : pc=(x,y,z,sum|c|), zero state & graph accum, stash W rows.
//  k_geo0 : per edge — gather pc[f],pc[t], compute geo=(len,dot1,dot2),
//           write rec, AND compute round-0 message
//             m0 = tanh(geo@Wg + b + sa_f*W11)      (h0 local, no gather!)
//           red.global.add.v4/v2 into state[dst].
//  rounds 1,2:
//    k_h    : h[n] = state[n]@Ws + b + sa*W11  (fp16, one 32B sector)
//    k_edge : m = tanh(h[src] + geo@Wg); vector-RED into state[dst]  (R7)
//  Readout: k_graph + k_out.
// ---------------------------------------------------------------------------

#define NMAX 200064
#define EMAX 6400000
#define GMAX 2048
#define SDP  12

struct __align__(32) HRow { uint4 a; uint2 b; uint2 pad; };

__device__ float4 g_state[NMAX * 3];   // (N,12) state, updated in place
__device__ HRow   g_hp[NMAX];          // h packed: 10 x fp16 in one 32B sector
__device__ float4 g_pc[NMAX];          // (x,y,z,sum|c|)
__device__ float4 g_gs[GMAX * 3];      // per-graph accum
__device__ float4 g_rec[EMAX];         // (len, dot1, dot2, src_as_int)
__device__ float  g_w[30];             // W rows 10 (len), 12 (dot1), 13 (dot2)

__device__ __forceinline__ float tanh_fast(float x) {
    float e = __expf(2.0f * x);
    return 1.0f - __fdividef(2.0f, e + 1.0f);
}
__device__ __forceinline__ void red_add4(float* p, float a, float b, float c, float d) {
    unsigned long long gp = __cvta_generic_to_global((void*)p);
    asm volatile("red.global.add.v4.f32 [%0], {%1,%2,%3,%4};"
                 :: "l"(gp), "f"(a), "f"(b), "f"(c), "f"(d) : "memory");
}
__device__ __forceinline__ void red_add2(float* p, float a, float b) {
    unsigned long long gp = __cvta_generic_to_global((void*)p);
    asm volatile("red.global.add.v2.f32 [%0], {%1,%2};"
                 :: "l"(gp), "f"(a), "f"(b) : "memory");
}

__device__ __forceinline__ void store_h(int n, const float* h) {
    __half2 p0 = __floats2half2_rn(h[0], h[1]);
    __half2 p1 = __floats2half2_rn(h[2], h[3]);
    __half2 p2 = __floats2half2_rn(h[4], h[5]);
    __half2 p3 = __floats2half2_rn(h[6], h[7]);
    __half2 p4 = __floats2half2_rn(h[8], h[9]);
    HRow r;
    r.a.x = *(unsigned int*)&p0;
    r.a.y = *(unsigned int*)&p1;
    r.a.z = *(unsigned int*)&p2;
    r.a.w = *(unsigned int*)&p3;
    r.b.x = *(unsigned int*)&p4;
    r.b.y = 0u;
    r.pad.x = 0u; r.pad.y = 0u;
    g_hp[n] = r;
}

// ---- init: pc, zero state & graph accum, stash edge-weight rows ----
__global__ void k_init(const float* __restrict__ coords,
                       const float* __restrict__ Wm, int N) {
    int n = blockIdx.x * blockDim.x + threadIdx.x;
    float4 z4 = make_float4(0.f, 0.f, 0.f, 0.f);
    if (n < N) {
        float x = coords[3 * n + 0];
        float y = coords[3 * n + 1];
        float z = coords[3 * n + 2];
        float sa = fabsf(x) + fabsf(y) + fabsf(z);
        g_pc[n] = make_float4(x, y, z, sa);
        g_state[n * 3 + 0] = z4;
        g_state[n * 3 + 1] = z4;
        g_state[n * 3 + 2] = z4;
    }
    if (n < GMAX) {
        g_gs[n * 3 + 0] = z4;
        g_gs[n * 3 + 1] = z4;
        g_gs[n * 3 + 2] = z4;
    }
    if (blockIdx.x == 0 && threadIdx.x < 10) {
        int j = threadIdx.x;
        g_w[j]      = __ldg(&Wm[100 + j]);
        g_w[10 + j] = __ldg(&Wm[120 + j]);
        g_w[20 + j] = __ldg(&Wm[130 + j]);
    }
}

// ---- fused build + round 0: geo precompute, rec write, m0 RED scatter ----
__global__ void __launch_bounds__(256)
k_geo0(const int* __restrict__ efrom, const int* __restrict__ eto,
       const float* __restrict__ elen, const float* __restrict__ evec,
       const float* __restrict__ Wm, const float* __restrict__ bm,
       int E, int T) {
    int tid = blockIdx.x * blockDim.x + threadIdx.x;
    float wl[10], w2[10], w3[10], w11[10], bb[10];
#pragma unroll
    for (int j = 0; j < 10; j++) {
        wl[j]  = __ldg(&Wm[100 + j]);
        w2[j]  = __ldg(&Wm[120 + j]);
        w3[j]  = __ldg(&Wm[130 + j]);
        w11[j] = __ldg(&Wm[110 + j]);
        bb[j]  = __ldg(&bm[j]);
    }
    float* stt = (float*)g_state;
    for (int e = tid; e < E; e += T) {
        int f = __ldg(&efrom[e]);
        int t = __ldg(&eto[e]);
        float4 cf = g_pc[f];
        float4 ct = g_pc[t];
        float len = __ldg(&elen[e]);
        float v0 = __ldg(&evec[3 * e + 0]);
        float v1 = __ldg(&evec[3 * e + 1]);
        float v2 = __ldg(&evec[3 * e + 2]);
        float dot1 = fmaf(cf.x, ct.x, fmaf(cf.y, ct.y, cf.z * ct.z));
        float dot2 = fmaf(cf.x, v0, fmaf(cf.y, v1, cf.z * v2));
        g_rec[e] = make_float4(len, dot1, dot2, __int_as_float(f));
        // round-0 message: h0 = b + sa*W11, all local
        float sa = cf.w;
        float m[10];
#pragma unroll
        for (int j = 0; j < 10; j++) {
            float h0 = fmaf(sa, w11[j], bb[j]);
            float a = fmaf(len, wl[j], fmaf(dot1, w2[j], fmaf(dot2, w3[j], h0)));
            m[j] = tanh_fast(a);
        }
        float* dst = stt + (size_t)t * SDP;
        red_add4(dst,     m[0], m[1], m[2], m[3]);
        red_add4(dst + 4, m[4], m[5], m[6], m[7]);
        red_add2(dst + 8, m[8], m[9]);
    }
}

// ---- per-node h = state@Ws + b + sa*W11 (fp16-packed) ----
__global__ void k_h(const float* __restrict__ Wm, const float* __restrict__ bm,
                    int N) {
    int n = blockIdx.x * blockDim.x + threadIdx.x;
    if (n >= N) return;
    const float4* srow = &g_state[n * 3];
    float4 s0 = srow[0], s1 = srow[1], s2 = srow[2];
    float s[10] = { s0.x, s0.y, s0.z, s0.w, s1.x, s1.y, s1.z, s1.w, s2.x, s2.y };
    float sa = g_pc[n].w;
    float h[10];
#pragma unroll
    for (int j = 0; j < 10; j++) {
        float acc = fmaf(sa, __ldg(&Wm[110 + j]), __ldg(&bm[j]));
#pragma unroll
        for (int i = 0; i < 10; i++)
            acc = fmaf(s[i], __ldg(&Wm[i * 10 + j]), acc);
        h[j] = acc;
    }
    store_h(n, h);
}

// ---- per-edge pass (R7 verbatim): 1-sector h gather + REDs ----
__global__ void __launch_bounds__(256)
k_edge(const int* __restrict__ eto, int E, int T) {
    int tid = blockIdx.x * blockDim.x + threadIdx.x;
    float wl[10], w2[10], w3[10];
#pragma unroll
    for (int j = 0; j < 10; j++) {
        wl[j] = g_w[j];
        w2[j] = g_w[10 + j];
        w3[j] = g_w[20 + j];
    }
    float* stt = (float*)g_state;
    for (int e = tid; e < E; e += T) {
        float4 r = __ldcs(&g_rec[e]);            // streaming: evict-first
        int t = __ldcs(&eto[e]);
        int f = __float_as_int(r.w);
        const HRow* hp = &g_hp[f];
        uint4 u = __ldg(&hp->a);                 // same 32B sector
        uint2 v = __ldg(&hp->b);
        float2 a0 = __half22float2(*(__half2*)&u.x);
        float2 a1 = __half22float2(*(__half2*)&u.y);
        float2 a2 = __half22float2(*(__half2*)&u.z);
        float2 a3 = __half22float2(*(__half2*)&u.w);
        float2 a4 = __half22float2(*(__half2*)&v.x);
        float hv[10] = { a0.x, a0.y, a1.x, a1.y, a2.x, a2.y, a3.x, a3.y, a4.x, a4.y };
        float m[10];
#pragma unroll
        for (int j = 0; j < 10; j++) {
            float a = fmaf(r.x, wl[j], fmaf(r.y, w2[j], fmaf(r.z, w3[j], hv[j])));
            m[j] = tanh_fast(a);
        }
        float* dst = stt + (size_t)t * SDP;
        red_add4(dst,     m[0], m[1], m[2], m[3]);
        red_add4(dst + 4, m[4], m[5], m[6], m[7]);
        red_add2(dst + 8, m[8], m[9]);
    }
}

// ---- graph segment sum ----
__global__ void k_graph(const int* __restrict__ gidx, int N) {
    int n = blockIdx.x * blockDim.x + threadIdx.x;
    if (n >= N) return;
    int g = gidx[n];
    const float4* srow = &g_state[n * 3];
    float4 s0 = srow[0], s1 = srow[1], s2 = srow[2];
    float* dst = (float*)&g_gs[g * 3];
    red_add4(dst,     s0.x, s0.y, s0.z, s0.w);
    red_add4(dst + 4, s1.x, s1.y, s1.z, s1.w);
    red_add2(dst + 8, s2.x, s2.y);
}

__device__ __forceinline__ float softplus_acc(float x) {
    if (x > 20.f) return x;
    return log1pf(expf(x));
}

__global__ void k_out(const float* __restrict__ Wo, const float* __restrict__ bo,
                      float* __restrict__ out, int G) {
    int g = blockIdx.x * blockDim.x + threadIdx.x;
    if (g >= G) return;
    const float* gs = (const float*)&g_gs[g * 3];
    float e[4];
#pragma unroll
    for (int j = 0; j < 4; j++) {
        float acc = __ldg(&bo[j]);
#pragma unroll
        for (int i = 0; i < 10; i++)
            acc = fmaf(gs[i], __ldg(&Wo[i * 4 + j]), acc);
        e[j] = acc;
    }
    out[4 * g + 0] = e[0];
    out[4 * g + 1] = softplus_acc(e[1]);
    out[4 * g + 2] = softplus_acc(e[2]) + 1.0f;
    out[4 * g + 3] = softplus_acc(e[3]);
}

extern "C" void kernel_launch(void* const* d_in, const int* in_sizes, int n_in,
                              void* d_out, int out_size) {
    const float* coords = (const float*)d_in[0];
    const float* elen   = (const float*)d_in[1];
    const float* evec   = (const float*)d_in[2];
    const float* Wm     = (const float*)d_in[3];
    const float* bm     = (const float*)d_in[4];
    const float* Wo     = (const float*)d_in[5];
    const float* bo     = (const float*)d_in[6];
    const int*   efrom  = (const int*)d_in[7];
    const int*   eto    = (const int*)d_in[8];
    const int*   gidx   = (const int*)d_in[9];
    float* out = (float*)d_out;

    int E = in_sizes[7];
    int N = in_sizes[9];
    int G = out_size / 4;

    const int TB = 256;
    int init_count = (N > GMAX) ? N : GMAX;
    int init_blocks = (init_count + TB - 1) / TB;
    int node_blocks = (N + TB - 1) / TB;
    long ethreads = ((long)E + 3) / 4;              // 4 edges/thread
    int eblocks = (int)((ethreads + TB - 1) / TB);
    int T = eblocks * TB;
    int gblocks = (G + TB - 1) / TB;

    k_init<<<init_blocks, TB>>>(coords, Wm, N);
    // fused build + round 0
    k_geo0<<<eblocks, TB>>>(efrom, eto, elen, evec, Wm, bm, E, T);
    // rounds 1, 2
    k_h<<<node_blocks, TB>>>(Wm, bm, N);
    k_edge<<<eblocks, TB>>>(eto, E, T);
    k_h<<<node_blocks, TB>>>(Wm, bm, N);
    k_edge<<<eblocks, TB>>>(eto, E, T);

    k_graph<<<node_blocks, TB>>>(gidx, N);
    k_out<<<gblocks, TB>>>(Wo, bo, out, G);
}

// round 11
// speedup vs baseline: 1.9277x; 1.0093x over previous
#include <cuda_runtime.h>
#include <cuda_fp16.h>
#include <math.h>

// ---------------------------------------------------------------------------
// EvidentialGNN3D — geo-precomputed, round-0 fused into the build, packed rec.
//  rec[e] = { dot1 f32, dot2 f32, len(f16)|dst_lo16, src(18b)|dst_hi2<<18 }
//  k_geo0 : gather pc[f],pc[t]; geo; write rec (streaming); round-0 message
//           m0 = tanh(geo@Wg + b + sa_f*W11); vector-RED into state[dst].
//  rounds 1,2:
//    k_h    : h[n] = state[n]@Ws + b + sa*W11  (fp16, one 32B sector)
//    k_edge : m = tanh(h[src] + geo@Wg); vector-RED into state[dst]
// ---------------------------------------------------------------------------

#define NMAX 200064
#define EMAX 6400000
#define GMAX 2048
#define SDP  12

struct __align__(32) HRow { uint4 a; uint2 b; uint2 pad; };

__device__ float4 g_state[NMAX * 3];   // (N,12) state, updated in place
__device__ HRow   g_hp[NMAX];          // h packed: 10 x fp16 in one 32B sector
__device__ float4 g_pc[NMAX];          // (x,y,z,sum|c|)
__device__ float4 g_gs[GMAX * 3];      // per-graph accum
__device__ uint4  g_rec[EMAX];         // packed records
__device__ float  g_w[30];             // W rows 10 (len), 12 (dot1), 13 (dot2)

__device__ __forceinline__ float tanh_fast(float x) {
    float e = __expf(2.0f * x);
    return 1.0f - __fdividef(2.0f, e + 1.0f);
}
__device__ __forceinline__ void red_add4(float* p, float a, float b, float c, float d) {
    unsigned long long gp = __cvta_generic_to_global((void*)p);
    asm volatile("red.global.add.v4.f32 [%0], {%1,%2,%3,%4};"
                 :: "l"(gp), "f"(a), "f"(b), "f"(c), "f"(d) : "memory");
}
__device__ __forceinline__ void red_add2(float* p, float a, float b) {
    unsigned long long gp = __cvta_generic_to_global((void*)p);
    asm volatile("red.global.add.v2.f32 [%0], {%1,%2};"
                 :: "l"(gp), "f"(a), "f"(b) : "memory");
}

__device__ __forceinline__ void store_h(int n, const float* h) {
    __half2 p0 = __floats2half2_rn(h[0], h[1]);
    __half2 p1 = __floats2half2_rn(h[2], h[3]);
    __half2 p2 = __floats2half2_rn(h[4], h[5]);
    __half2 p3 = __floats2half2_rn(h[6], h[7]);
    __half2 p4 = __floats2half2_rn(h[8], h[9]);
    HRow r;
    r.a.x = *(unsigned int*)&p0;
    r.a.y = *(unsigned int*)&p1;
    r.a.z = *(unsigned int*)&p2;
    r.a.w = *(unsigned int*)&p3;
    r.b.x = *(unsigned int*)&p4;
    r.b.y = 0u;
    r.pad.x = 0u; r.pad.y = 0u;
    g_hp[n] = r;
}

// ---- init: pc, zero state & graph accum, stash edge-weight rows ----
__global__ void k_init(const float* __restrict__ coords,
                       const float* __restrict__ Wm, int N) {
    int n = blockIdx.x * blockDim.x + threadIdx.x;
    float4 z4 = make_float4(0.f, 0.f, 0.f, 0.f);
    if (n < N) {
        float x = coords[3 * n + 0];
        float y = coords[3 * n + 1];
        float z = coords[3 * n + 2];
        float sa = fabsf(x) + fabsf(y) + fabsf(z);
        g_pc[n] = make_float4(x, y, z, sa);
        g_state[n * 3 + 0] = z4;
        g_state[n * 3 + 1] = z4;
        g_state[n * 3 + 2] = z4;
    }
    if (n < GMAX) {
        g_gs[n * 3 + 0] = z4;
        g_gs[n * 3 + 1] = z4;
        g_gs[n * 3 + 2] = z4;
    }
    if (blockIdx.x == 0 && threadIdx.x < 10) {
        int j = threadIdx.x;
        g_w[j]      = __ldg(&Wm[100 + j]);
        g_w[10 + j] = __ldg(&Wm[120 + j]);
        g_w[20 + j] = __ldg(&Wm[130 + j]);
    }
}

// ---- fused build + round 0 ----
__global__ void __launch_bounds__(256)
k_geo0(const int* __restrict__ efrom, const int* __restrict__ eto,
       const float* __restrict__ elen, const float* __restrict__ evec,
       const float* __restrict__ Wm, const float* __restrict__ bm,
       int E, int T) {
    int tid = blockIdx.x * blockDim.x + threadIdx.x;
    float wl[10], w2[10], w3[10], w11[10], bb[10];
#pragma unroll
    for (int j = 0; j < 10; j++) {
        wl[j]  = __ldg(&Wm[100 + j]);
        w2[j]  = __ldg(&Wm[120 + j]);
        w3[j]  = __ldg(&Wm[130 + j]);
        w11[j] = __ldg(&Wm[110 + j]);
        bb[j]  = __ldg(&bm[j]);
    }
    float* stt = (float*)g_state;
    for (int e = tid; e < E; e += T) {
        int f = __ldcs(&efrom[e]);
        int t = __ldcs(&eto[e]);
        float4 cf = g_pc[f];
        float4 ct = g_pc[t];
        float len = __ldcs(&elen[e]);
        float v0 = __ldcs(&evec[3 * e + 0]);
        float v1 = __ldcs(&evec[3 * e + 1]);
        float v2 = __ldcs(&evec[3 * e + 2]);
        float dot1 = fmaf(cf.x, ct.x, fmaf(cf.y, ct.y, cf.z * ct.z));
        float dot2 = fmaf(cf.x, v0, fmaf(cf.y, v1, cf.z * v2));
        uint4 r;
        r.x = __float_as_uint(dot1);
        r.y = __float_as_uint(dot2);
        r.z = (unsigned int)__half_as_ushort(__float2half_rn(len))
            | (((unsigned int)t & 0xFFFFu) << 16);
        r.w = (unsigned int)f | (((unsigned int)t >> 16) << 18);
        __stcs(&g_rec[e], r);
        // round-0 message: h0 = b + sa*W11, all local
        float sa = cf.w;
        float m[10];
#pragma unroll
        for (int j = 0; j < 10; j++) {
            float h0 = fmaf(sa, w11[j], bb[j]);
            float a = fmaf(len, wl[j], fmaf(dot1, w2[j], fmaf(dot2, w3[j], h0)));
            m[j] = tanh_fast(a);
        }
        float* dst = stt + (size_t)t * SDP;
        red_add4(dst,     m[0], m[1], m[2], m[3]);
        red_add4(dst + 4, m[4], m[5], m[6], m[7]);
        red_add2(dst + 8, m[8], m[9]);
    }
}

// ---- per-node h = state@Ws + b + sa*W11 (fp16-packed) ----
__global__ void k_h(const float* __restrict__ Wm, const float* __restrict__ bm,
                    int N) {
    int n = blockIdx.x * blockDim.x + threadIdx.x;
    if (n >= N) return;
    const float4* srow = &g_state[n * 3];
    float4 s0 = srow[0], s1 = srow[1], s2 = srow[2];
    float s[10] = { s0.x, s0.y, s0.z, s0.w, s1.x, s1.y, s1.z, s1.w, s2.x, s2.y };
    float sa = g_pc[n].w;
    float h[10];
#pragma unroll
    for (int j = 0; j < 10; j++) {
        float acc = fmaf(sa, __ldg(&Wm[110 + j]), __ldg(&bm[j]));
#pragma unroll
        for (int i = 0; i < 10; i++)
            acc = fmaf(s[i], __ldg(&Wm[i * 10 + j]), acc);
        h[j] = acc;
    }
    store_h(n, h);
}

// ---- per-edge pass: packed rec (no eto), 1-sector h gather, REDs ----
__global__ void __launch_bounds__(256)
k_edge(int E, int T) {
    int tid = blockIdx.x * blockDim.x + threadIdx.x;
    float wl[10], w2[10], w3[10];
#pragma unroll
    for (int j = 0; j < 10; j++) {
        wl[j] = g_w[j];
        w2[j] = g_w[10 + j];
        w3[j] = g_w[20 + j];
    }
    float* stt = (float*)g_state;
    for (int e = tid; e < E; e += T) {
        uint4 r = __ldcs(&g_rec[e]);             // streaming: evict-first
        float dot1 = __uint_as_float(r.x);
        float dot2 = __uint_as_float(r.y);
        float len = __half2float(__ushort_as_half((unsigned short)(r.z & 0xFFFFu)));
        int t = (int)(r.z >> 16) | (int)(((r.w >> 18) & 3u) << 16);
        int f = (int)(r.w & 0x3FFFFu);
        const HRow* hp = &g_hp[f];
        uint4 u = __ldg(&hp->a);                 // same 32B sector
        uint2 v = __ldg(&hp->b);
        float2 a0 = __half22float2(*(__half2*)&u.x);
        float2 a1 = __half22float2(*(__half2*)&u.y);
        float2 a2 = __half22float2(*(__half2*)&u.z);
        float2 a3 = __half22float2(*(__half2*)&u.w);
        float2 a4 = __half22float2(*(__half2*)&v.x);
        float hv[10] = { a0.x, a0.y, a1.x, a1.y, a2.x, a2.y, a3.x, a3.y, a4.x, a4.y };
        float m[10];
#pragma unroll
        for (int j = 0; j < 10; j++) {
            float a = fmaf(len, wl[j], fmaf(dot1, w2[j], fmaf(dot2, w3[j], hv[j])));
            m[j] = tanh_fast(a);
        }
        float* dst = stt + (size_t)t * SDP;
        red_add4(dst,     m[0], m[1], m[2], m[3]);
        red_add4(dst + 4, m[4], m[5], m[6], m[7]);
        red_add2(dst + 8, m[8], m[9]);
    }
}

// ---- graph segment sum ----
__global__ void k_graph(const int* __restrict__ gidx, int N) {
    int n = blockIdx.x * blockDim.x + threadIdx.x;
    if (n >= N) return;
    int g = gidx[n];
    const float4* srow = &g_state[n * 3];
    float4 s0 = srow[0], s1 = srow[1], s2 = srow[2];
    float* dst = (float*)&g_gs[g * 3];
    red_add4(dst,     s0.x, s0.y, s0.z, s0.w);
    red_add4(dst + 4, s1.x, s1.y, s1.z, s1.w);
    red_add2(dst + 8, s2.x, s2.y);
}

__device__ __forceinline__ float softplus_acc(float x) {
    if (x > 20.f) return x;
    return log1pf(expf(x));
}

__global__ void k_out(const float* __restrict__ Wo, const float* __restrict__ bo,
                      float* __restrict__ out, int G) {
    int g = blockIdx.x * blockDim.x + threadIdx.x;
    if (g >= G) return;
    const float* gs = (const float*)&g_gs[g * 3];
    float e[4];
#pragma unroll
    for (int j = 0; j < 4; j++) {
        float acc = __ldg(&bo[j]);
#pragma unroll
        for (int i = 0; i < 10; i++)
            acc = fmaf(gs[i], __ldg(&Wo[i * 4 + j]), acc);
        e[j] = acc;
    }
    out[4 * g + 0] = e[0];
    out[4 * g + 1] = softplus_acc(e[1]);
    out[4 * g + 2] = softplus_acc(e[2]) + 1.0f;
    out[4 * g + 3] = softplus_acc(e[3]);
}

extern "C" void kernel_launch(void* const* d_in, const int* in_sizes, int n_in,
                              void* d_out, int out_size) {
    const float* coords = (const float*)d_in[0];
    const float* elen   = (const float*)d_in[1];
    const float* evec   = (const float*)d_in[2];
    const float* Wm     = (const float*)d_in[3];
    const float* bm     = (const float*)d_in[4];
    const float* Wo     = (const float*)d_in[5];
    const float* bo     = (const float*)d_in[6];
    const int*   efrom  = (const int*)d_in[7];
    const int*   eto    = (const int*)d_in[8];
    const int*   gidx   = (const int*)d_in[9];
    float* out = (float*)d_out;

    int E = in_sizes[7];
    int N = in_sizes[9];
    int G = out_size / 4;

    const int TB = 256;
    int init_count = (N > GMAX) ? N : GMAX;
    int init_blocks = (init_count + TB - 1) / TB;
    int node_blocks = (N + TB - 1) / TB;
    long ethreads = ((long)E + 3) / 4;              // 4 edges/thread
    int eblocks = (int)((ethreads + TB - 1) / TB);
    int T = eblocks * TB;
    int gblocks = (G + TB - 1) / TB;

    k_init<<<init_blocks, TB>>>(coords, Wm, N);
    // fused build + round 0
    k_geo0<<<eblocks, TB>>>(efrom, eto, elen, evec, Wm, bm, E, T);
    // rounds 1, 2
    k_h<<<node_blocks, TB>>>(Wm, bm, N);
    k_edge<<<eblocks, TB>>>(E, T);
    k_h<<<node_blocks, TB>>>(Wm, bm, N);
    k_edge<<<eblocks, TB>>>(E, T);

    k_graph<<<node_blocks, TB>>>(gidx, N);
    k_out<<<gblocks, TB>>>(Wo, bo, out, G);
}